// round 5
// baseline (speedup 1.0000x reference)
#include <cuda_runtime.h>
#include <math.h>

// Shapes fixed by the problem definition.
#define BATCH 4
#define T1    2048
#define T2    2048
#define NFEAT 1024
#define NH    16
#define DK    64

// Attention tiling: BQ=128 query rows, BK=64 kv rows, 256 threads (16x16),
// micro-tile 8(row) x 4(col) for S and 8(row) x 4(d) for O.
#define BQ    128
#define BK    64
#define QSTR  64      // Q row stride (reads are tx-broadcast -> no pad needed)
#define KSTR  64      // K stored [d][j], j-float4-groups XOR-swizzled by d>>2
#define VSTR  64
#define PSTR  68      // P row stride (pad keeps f4 alignment)

#define ATTN_SMEM_FLOATS (BQ*QSTR + DK*KSTR + BK*VSTR + BQ*PSTR)
#define ATTN_SMEM_BYTES  (ATTN_SMEM_FLOATS * 4)   // 100,352 B -> 2 CTAs/SM

// Scratch (no dynamic allocation allowed): projected Q + mask compaction.
__device__ float g_qproj[BATCH * T1 * NFEAT];      // ~33.5 MB
__device__ int   g_valid_idx[BATCH * T2];
__device__ int   g_valid_cnt[BATCH];

__device__ __forceinline__ void prefetch_l2(const void* p) {
    asm volatile("prefetch.global.L2 [%0];" :: "l"(p));
}

// ---------------------------------------------------------------------------
// Kernel 1: per-batch compaction of valid (mask != 0) column indices.
// ---------------------------------------------------------------------------
__global__ void compact_mask_kernel(const int* __restrict__ mask) {
    const int b = blockIdx.x;
    const int lane = threadIdx.x;
    const int* m = mask + b * T2;
    int cnt = 0;
    for (int base = 0; base < T2; base += 32) {
        const int v = m[base + lane];
        const unsigned bal = __ballot_sync(0xffffffffu, v != 0);
        if (v)
            g_valid_idx[b * T2 + cnt + __popc(bal & ((1u << lane) - 1u))] = base + lane;
        cnt += __popc(bal);
    }
    if (lane == 0) g_valid_cnt[b] = cnt;
}

// ---------------------------------------------------------------------------
// Kernel 2: Q projection GEMM.  C[8192,1024] = A * W^T + bias.
// 128x128 tile, BK=16, 256 threads, 8x8 per thread, 2-stage double buffer.
// FFMA-bound at ~442 us chip floor; loads fully hidden by prefetch-to-reg.
// ---------------------------------------------------------------------------
__global__ __launch_bounds__(256, 2)
void qproj_kernel(const float* __restrict__ A, const float* __restrict__ W,
                  const float* __restrict__ bias) {
    __shared__ float As[2][16][132];
    __shared__ float Bs[2][16][132];
    const int tid = threadIdx.x;
    const int tx = tid & 15, ty = tid >> 4;
    const int bm = blockIdx.y * 128;
    const int bn = blockIdx.x * 128;

    int ldrow[2], ldkc[2];
#pragma unroll
    for (int p = 0; p < 2; p++) {
        const int idx = tid + p * 256;
        ldrow[p] = idx >> 2;
        ldkc[p]  = (idx & 3) << 2;
    }

    float acc[8][8];
#pragma unroll
    for (int i = 0; i < 8; i++)
#pragma unroll
        for (int j = 0; j < 8; j++) acc[i][j] = 0.f;

    float4 pa[2], pw[2];
#pragma unroll
    for (int p = 0; p < 2; p++) {
        pa[p] = *(const float4*)(A + (size_t)(bm + ldrow[p]) * NFEAT + ldkc[p]);
        pw[p] = *(const float4*)(W + (size_t)(bn + ldrow[p]) * NFEAT + ldkc[p]);
    }
#pragma unroll
    for (int p = 0; p < 2; p++) {
        As[0][ldkc[p] + 0][ldrow[p]] = pa[p].x; As[0][ldkc[p] + 1][ldrow[p]] = pa[p].y;
        As[0][ldkc[p] + 2][ldrow[p]] = pa[p].z; As[0][ldkc[p] + 3][ldrow[p]] = pa[p].w;
        Bs[0][ldkc[p] + 0][ldrow[p]] = pw[p].x; Bs[0][ldkc[p] + 1][ldrow[p]] = pw[p].y;
        Bs[0][ldkc[p] + 2][ldrow[p]] = pw[p].z; Bs[0][ldkc[p] + 3][ldrow[p]] = pw[p].w;
    }
    __syncthreads();

    int buf = 0;
    const int KT = NFEAT / 16;   // 64
    for (int kt = 0; kt < KT; kt++) {
        if (kt + 1 < KT) {
            const int k0 = (kt + 1) * 16;
#pragma unroll
            for (int p = 0; p < 2; p++) {
                pa[p] = *(const float4*)(A + (size_t)(bm + ldrow[p]) * NFEAT + k0 + ldkc[p]);
                pw[p] = *(const float4*)(W + (size_t)(bn + ldrow[p]) * NFEAT + k0 + ldkc[p]);
            }
        }
#pragma unroll
        for (int k = 0; k < 16; k++) {
            float av[8], bv[8];
            *(float4*)&av[0] = *(const float4*)&As[buf][k][ty * 4];
            *(float4*)&av[4] = *(const float4*)&As[buf][k][64 + ty * 4];
            *(float4*)&bv[0] = *(const float4*)&Bs[buf][k][tx * 4];
            *(float4*)&bv[4] = *(const float4*)&Bs[buf][k][64 + tx * 4];
#pragma unroll
            for (int i = 0; i < 8; i++)
#pragma unroll
                for (int j = 0; j < 8; j++)
                    acc[i][j] = fmaf(av[i], bv[j], acc[i][j]);
        }
        if (kt + 1 < KT) {
            const int nb = buf ^ 1;
#pragma unroll
            for (int p = 0; p < 2; p++) {
                As[nb][ldkc[p] + 0][ldrow[p]] = pa[p].x; As[nb][ldkc[p] + 1][ldrow[p]] = pa[p].y;
                As[nb][ldkc[p] + 2][ldrow[p]] = pa[p].z; As[nb][ldkc[p] + 3][ldrow[p]] = pa[p].w;
                Bs[nb][ldkc[p] + 0][ldrow[p]] = pw[p].x; Bs[nb][ldkc[p] + 1][ldrow[p]] = pw[p].y;
                Bs[nb][ldkc[p] + 2][ldrow[p]] = pw[p].z; Bs[nb][ldkc[p] + 3][ldrow[p]] = pw[p].w;
            }
            buf = nb;
            __syncthreads();
        }
    }

#pragma unroll
    for (int ch = 0; ch < 2; ch++) {
        const int n0 = bn + ch * 64 + tx * 4;
        const float4 bv = *(const float4*)(bias + n0);
#pragma unroll
        for (int rh = 0; rh < 2; rh++) {
#pragma unroll
            for (int r = 0; r < 4; r++) {
                const int m = bm + rh * 64 + ty * 4 + r;
                float4 o;
                o.x = acc[rh * 4 + r][ch * 4 + 0] + bv.x;
                o.y = acc[rh * 4 + r][ch * 4 + 1] + bv.y;
                o.z = acc[rh * 4 + r][ch * 4 + 2] + bv.z;
                o.w = acc[rh * 4 + r][ch * 4 + 3] + bv.w;
                *(float4*)(g_qproj + (size_t)m * NFEAT + n0) = o;
            }
        }
    }
}

// ---------------------------------------------------------------------------
// Kernel 3: fused masked attention over COMPACTED KV columns.
// Block = (b, h, 128-query tile); 256 threads; KV tiles of 64 compacted rows.
// smem 98 KB -> 2 CTAs/SM.  Next tile's K/V rows are L2-prefetched during the
// current gather so each gather hits L2 (~250cyc) instead of DRAM (~600+).
// ---------------------------------------------------------------------------
__global__ __launch_bounds__(256, 2)
void attn_kernel(const float* __restrict__ key, const float* __restrict__ value,
                 float* __restrict__ out) {
    extern __shared__ float sm[];
    float* Qs = sm;                    // [128][64]
    float* Ks = Qs + BQ * QSTR;        // [64 d][64 j] group-swizzled
    float* Vs = Ks + DK * KSTR;        // [64 j][64 d]
    float* Ps = Vs + BK * VSTR;        // [128][68]

    const int tid = threadIdx.x;
    const int tx = tid & 15, ty = tid >> 4;
    const int blk = blockIdx.x;
    const int qt = blk & 15;           // T1/BQ = 16
    const int h  = (blk >> 4) & 15;
    const int b  = blk >> 8;
    const int q0 = qt * BQ;

    const int cnt = g_valid_cnt[b];
    const float* kbase = key   + (size_t)b * T2 * NFEAT + h * DK;
    const float* vbase = value + (size_t)b * T2 * NFEAT + h * DK;
    const int* vidx = g_valid_idx + b * T2;

    float o[8][4];
    float mrow[8], lrow[8];
#pragma unroll
    for (int r = 0; r < 8; r++) {
        mrow[r] = -INFINITY; lrow[r] = 0.f;
#pragma unroll
        for (int c = 0; c < 4; c++) o[r][c] = 0.f;
    }

    if (cnt == 0) {
        const float4 z = make_float4(0.f, 0.f, 0.f, 0.f);
#pragma unroll
        for (int r = 0; r < 8; r++)
            *(float4*)(out + (size_t)(b * T1 + q0 + ty * 8 + r) * NFEAT + h * DK + tx * 4) = z;
        return;
    }

    // ---- load Q tile once: 128 rows x 16 f4 chunks = 2048 f4 / 256 thr ----
#pragma unroll
    for (int p = 0; p < 8; p++) {
        const int idx = tid + p * 256;
        const int i  = idx >> 4;
        const int dc = idx & 15;
        *(float4*)&Qs[i * QSTR + dc * 4] =
            *(const float4*)(g_qproj + (size_t)(b * T1 + q0 + i) * NFEAT + h * DK + dc * 4);
    }

    const int ntiles = (cnt + BK - 1) / BK;
    for (int t = 0; t < ntiles; t++) {
        const int kv0 = t * BK;
        __syncthreads();   // prior tile fully consumed (covers Q load at t=0)

        // ---- gather K (transposed + group-swizzled) and V (row-major);
        //      simultaneously L2-prefetch next tile's rows (pure hint) ----
#pragma unroll
        for (int p = 0; p < 4; p++) {
            const int idx = tid + p * 256;
            const int j  = idx >> 4;        // 0..63
            const int dc = idx & 15;
            const int jg = kv0 + j;
            const int row = vidx[(jg < cnt) ? jg : 0];
            const float4 kv = *(const float4*)(kbase + (size_t)row * NFEAT + dc * 4);
            const float4 vv = *(const float4*)(vbase + (size_t)row * NFEAT + dc * 4);
            const int jn = jg + BK;
            if (jn < cnt) {
                const int nrow = vidx[jn];
                prefetch_l2(kbase + (size_t)nrow * NFEAT + dc * 4);
                prefetch_l2(vbase + (size_t)nrow * NFEAT + dc * 4);
            }
            // K element (j, d): group ((j>>2)^dc), word j&3, rows d=dc*4..+3
            float* kd = &Ks[(dc * 4) * KSTR + (((j >> 2) ^ dc) << 2) + (j & 3)];
            kd[0 * KSTR] = kv.x; kd[1 * KSTR] = kv.y;
            kd[2 * KSTR] = kv.z; kd[3 * KSTR] = kv.w;
            *(float4*)&Vs[j * VSTR + dc * 4] = vv;
        }
        __syncthreads();

        // ---- S = Q K^T : 8 rows x 4 cols per thread, split in row-halves ----
        float s[8][4];
#pragma unroll
        for (int r = 0; r < 8; r++)
#pragma unroll
            for (int c = 0; c < 4; c++) s[r][c] = 0.f;

        for (int d4 = 0; d4 < DK; d4 += 4) {
            const int dq = d4 >> 2;
            float4 kv4[4];
#pragma unroll
            for (int dd = 0; dd < 4; dd++)
                kv4[dd] = *(const float4*)&Ks[(d4 + dd) * KSTR + ((tx ^ dq) << 2)];
#pragma unroll
            for (int half = 0; half < 2; half++) {
                float4 qv[4];
#pragma unroll
                for (int r = 0; r < 4; r++)
                    qv[r] = *(const float4*)&Qs[(ty * 8 + half * 4 + r) * QSTR + d4];
#pragma unroll
                for (int dd = 0; dd < 4; dd++) {
                    const float kc[4] = {((const float*)&kv4[dd])[0], ((const float*)&kv4[dd])[1],
                                         ((const float*)&kv4[dd])[2], ((const float*)&kv4[dd])[3]};
#pragma unroll
                    for (int r = 0; r < 4; r++) {
                        const float qq = ((const float*)&qv[r])[dd];
#pragma unroll
                        for (int c = 0; c < 4; c++)
                            s[half * 4 + r][c] = fmaf(qq, kc[c], s[half * 4 + r][c]);
                    }
                }
            }
        }

        // ---- scale, tail-mask, online softmax (row spread over 16 tx lanes) ----
#pragma unroll
        for (int r = 0; r < 8; r++) {
#pragma unroll
            for (int c = 0; c < 4; c++) {
                const int jg = kv0 + tx * 4 + c;
                s[r][c] = (jg < cnt) ? s[r][c] * 0.125f : -INFINITY;
            }
            float v = fmaxf(fmaxf(s[r][0], s[r][1]), fmaxf(s[r][2], s[r][3]));
#pragma unroll
            for (int off = 8; off > 0; off >>= 1)
                v = fmaxf(v, __shfl_xor_sync(0xffffffffu, v, off, 16));
            const float mnew = fmaxf(mrow[r], v);
            const float corr = __expf(mrow[r] - mnew);   // 0 on first tile
            mrow[r] = mnew;
            float rsum = 0.f;
#pragma unroll
            for (int c = 0; c < 4; c++) {
                const float pv = __expf(s[r][c] - mnew);  // masked -> exactly 0
                s[r][c] = pv;
                rsum += pv;
            }
#pragma unroll
            for (int off = 8; off > 0; off >>= 1)
                rsum += __shfl_xor_sync(0xffffffffu, rsum, off, 16);
            lrow[r] = lrow[r] * corr + rsum;
#pragma unroll
            for (int c = 0; c < 4; c++) o[r][c] *= corr;
        }

        // ---- store P; exchange is intra-warp (reader/writer share ty); the
        //      two __syncthreads above order next-tile overwrite vs readers ----
#pragma unroll
        for (int r = 0; r < 8; r++)
            *(float4*)&Ps[(ty * 8 + r) * PSTR + tx * 4] =
                make_float4(s[r][0], s[r][1], s[r][2], s[r][3]);
        __syncwarp();

        // ---- O += P V : 8 rows x 4 d-cols, split in row-halves ----
        for (int j4 = 0; j4 < BK; j4 += 4) {
            float4 vv4[4];
#pragma unroll
            for (int jj = 0; jj < 4; jj++)
                vv4[jj] = *(const float4*)&Vs[(j4 + jj) * VSTR + tx * 4];
#pragma unroll
            for (int half = 0; half < 2; half++) {
#pragma unroll
                for (int r = 0; r < 4; r++) {
                    const float4 pvec = *(const float4*)&Ps[(ty * 8 + half * 4 + r) * PSTR + j4];
                    const float pp[4] = {pvec.x, pvec.y, pvec.z, pvec.w};
#pragma unroll
                    for (int jj = 0; jj < 4; jj++) {
                        const float* vc = (const float*)&vv4[jj];
#pragma unroll
                        for (int c = 0; c < 4; c++)
                            o[half * 4 + r][c] = fmaf(pp[jj], vc[c], o[half * 4 + r][c]);
                    }
                }
            }
        }
    }

    // ---- normalize and store ----
#pragma unroll
    for (int r = 0; r < 8; r++) {
        const float inv = 1.0f / lrow[r];
        float4 ov;
        ov.x = o[r][0] * inv; ov.y = o[r][1] * inv;
        ov.z = o[r][2] * inv; ov.w = o[r][3] * inv;
        *(float4*)(out + (size_t)(b * T1 + q0 + ty * 8 + r) * NFEAT + h * DK + tx * 4) = ov;
    }
}

// ---------------------------------------------------------------------------
// Entry point.  Inputs per metadata order: query, key, value, mask, Wq, bq.
// ---------------------------------------------------------------------------
extern "C" void kernel_launch(void* const* d_in, const int* in_sizes, int n_in,
                              void* d_out, int out_size) {
    const float* query = (const float*)d_in[0];
    const float* key   = (const float*)d_in[1];
    const float* value = (const float*)d_in[2];
    const int*   mask  = (const int*)  d_in[3];
    const float* Wq    = (const float*)d_in[4];
    const float* bq    = (const float*)d_in[5];
    float* out = (float*)d_out;

    // >48KB dynamic smem opt-in (host attribute; idempotent; capture-legal).
    cudaFuncSetAttribute(attn_kernel,
                         cudaFuncAttributeMaxDynamicSharedMemorySize,
                         ATTN_SMEM_BYTES);

    compact_mask_kernel<<<BATCH, 32>>>(mask);
    qproj_kernel<<<dim3(NFEAT / 128, (BATCH * T1) / 128), 256>>>(query, Wq, bq);
    attn_kernel<<<BATCH * NH * (T1 / BQ), 256, ATTN_SMEM_BYTES>>>(key, value, out);
}

// round 8
// speedup vs baseline: 2.4126x; 2.4126x over previous
#include <cuda_runtime.h>
#include <cuda_bf16.h>
#include <math.h>
#include <stdint.h>

// Shapes fixed by the problem definition.
#define BATCH 4
#define T1    2048
#define T2    2048
#define NFEAT 1024
#define NH    16
#define DK    64

// Attention tiling: BQ=128 rows (8 warps x 16), BK=64 kv cols, 256 threads.
#define BQ    128
#define BK    64

#define ATTN_SMEM_BYTES  65536   // Qh,Ql[128][64] + Kh,Kl[64][64] + Vh,Vl[64][64] bf16
#define QPROJ_SMEM_BYTES 65536   // Ah,Al[128][64] + Wh,Wl[128][64] bf16

// Scratch (no dynamic allocation allowed): projected Q + mask compaction.
__device__ float g_qproj[BATCH * T1 * NFEAT];      // ~33.5 MB
__device__ int   g_valid_idx[BATCH * T2];
__device__ int   g_valid_cnt[BATCH];

__device__ __forceinline__ void prefetch_l2(const void* p) {
    asm volatile("prefetch.global.L2 [%0];" :: "l"(p));
}

// ---- bf16 split helpers -------------------------------------------------
__device__ __forceinline__ uint32_t pack_bf16(float x, float y) {
    __nv_bfloat162 t = __floats2bfloat162_rn(x, y);   // .x = x (low 16 bits)
    return *reinterpret_cast<uint32_t*>(&t);
}
__device__ __forceinline__ float bf16_res(float x) {
    return x - __bfloat162float(__float2bfloat16_rn(x));
}

// ---- smem swizzle: row-major [row][64] bf16, 8 x 16B chunks per 128B row.
// chunk' = chunk ^ (row & 7)  -> ldmatrix over 8 consecutive rows is conflict-free.
__device__ __forceinline__ uint32_t swzb(int row, int ch) {
    return (uint32_t)(row * 128 + (((ch) ^ (row & 7)) << 4));
}

// ---- tensor-core wrappers ----------------------------------------------
__device__ __forceinline__ void ldsm_x4(uint32_t* r, uint32_t addr) {
    asm volatile("ldmatrix.sync.aligned.m8n8.x4.shared.b16 {%0,%1,%2,%3}, [%4];"
        : "=r"(r[0]), "=r"(r[1]), "=r"(r[2]), "=r"(r[3]) : "r"(addr));
}
__device__ __forceinline__ void ldsm_x4_t(uint32_t* r, uint32_t addr) {
    asm volatile("ldmatrix.sync.aligned.m8n8.x4.trans.shared.b16 {%0,%1,%2,%3}, [%4];"
        : "=r"(r[0]), "=r"(r[1]), "=r"(r[2]), "=r"(r[3]) : "r"(addr));
}
__device__ __forceinline__ void mma16816(float* c, const uint32_t* a, uint32_t b0, uint32_t b1) {
    asm volatile("mma.sync.aligned.m16n8k16.row.col.f32.bf16.bf16.f32 "
        "{%0,%1,%2,%3}, {%4,%5,%6,%7}, {%8,%9}, {%0,%1,%2,%3};"
        : "+f"(c[0]), "+f"(c[1]), "+f"(c[2]), "+f"(c[3])
        : "r"(a[0]), "r"(a[1]), "r"(a[2]), "r"(a[3]), "r"(b0), "r"(b1));
}

// Convert 8 consecutive fp32 into hi/lo bf16 16B chunks at swizzled (row, c).
__device__ __forceinline__ void store_hl(unsigned char* H, unsigned char* L,
                                         int row, int c, float4 f0, float4 f1) {
    uint4 hh, ll;
    hh.x = pack_bf16(f0.x, f0.y); hh.y = pack_bf16(f0.z, f0.w);
    hh.z = pack_bf16(f1.x, f1.y); hh.w = pack_bf16(f1.z, f1.w);
    ll.x = pack_bf16(bf16_res(f0.x), bf16_res(f0.y));
    ll.y = pack_bf16(bf16_res(f0.z), bf16_res(f0.w));
    ll.z = pack_bf16(bf16_res(f1.x), bf16_res(f1.y));
    ll.w = pack_bf16(bf16_res(f1.z), bf16_res(f1.w));
    const uint32_t off = swzb(row, c);
    *(uint4*)(H + off) = hh;
    *(uint4*)(L + off) = ll;
}

// ---------------------------------------------------------------------------
// Kernel 1: per-batch compaction of valid (mask != 0) column indices.
// ---------------------------------------------------------------------------
__global__ void compact_mask_kernel(const int* __restrict__ mask) {
    const int b = blockIdx.x;
    const int lane = threadIdx.x;
    const int* m = mask + b * T2;
    int cnt = 0;
    for (int base = 0; base < T2; base += 32) {
        const int v = m[base + lane];
        const unsigned bal = __ballot_sync(0xffffffffu, v != 0);
        if (v)
            g_valid_idx[b * T2 + cnt + __popc(bal & ((1u << lane) - 1u))] = base + lane;
        cnt += __popc(bal);
    }
    if (lane == 0) g_valid_cnt[b] = cnt;
}

// ---------------------------------------------------------------------------
// Kernel 2: Q projection GEMM on tensor cores (split-bf16, 3-pass).
// C[8192,1024] = A[M,K] * W[N,K]^T + bias.  Both operands K-major => exactly
// the audited Q*K^T fragment pattern from the attention S-loop.
// Block tile 128(M) x 128(N); 8 warps, warp w owns rows w*16..+16 x all 128 N.
// K staged through smem in 64-wide chunks (Ah/Al/Wh/Wl, 64 KB -> 2 CTAs/SM).
// ---------------------------------------------------------------------------
__global__ __launch_bounds__(256, 2)
void qproj_kernel(const float* __restrict__ A, const float* __restrict__ W,
                  const float* __restrict__ bias) {
    extern __shared__ __align__(16) unsigned char qsm[];
    unsigned char* Ah = qsm;               // 128*128B = 16384
    unsigned char* Al = qsm + 16384;
    unsigned char* Wh = qsm + 32768;
    unsigned char* Wl = qsm + 49152;       // end 65536

    const uint32_t sAh = (uint32_t)__cvta_generic_to_shared(Ah);
    const uint32_t sAl = (uint32_t)__cvta_generic_to_shared(Al);
    const uint32_t sWh = (uint32_t)__cvta_generic_to_shared(Wh);
    const uint32_t sWl = (uint32_t)__cvta_generic_to_shared(Wl);

    const int tid  = threadIdx.x;
    const int lane = tid & 31;
    const int w    = tid >> 5;
    const int bm   = blockIdx.y * 128;
    const int bn   = blockIdx.x * 128;

    float s[16][4];
#pragma unroll
    for (int tt = 0; tt < 16; tt++)
#pragma unroll
        for (int r = 0; r < 4; r++) s[tt][r] = 0.f;

    const int lrow = tid >> 3;       // 0..127 (load row)
    const int lc   = tid & 7;        // 0..7  (16B chunk)

    for (int kc = 0; kc < NFEAT / 64; kc++) {
        const int k0 = kc * 64;
        __syncthreads();   // previous chunk consumed
        // ---- load + convert A[128][64] and W[128][64] (4 rows each/thread) --
#pragma unroll
        for (int p = 0; p < 4; p++) {
            const int row = lrow + p * 32;   // wrong stride? no: 256 thr/8 = 32 rows per pass
            const float* asrc = A + (size_t)(bm + row) * NFEAT + k0 + lc * 8;
            const float* wsrc = W + (size_t)(bn + row) * NFEAT + k0 + lc * 8;
            if (kc + 1 < NFEAT / 64) {
                prefetch_l2(asrc + 64);
                prefetch_l2(wsrc + 64);
            }
            store_hl(Ah, Al, row, lc, *(const float4*)asrc, *(const float4*)(asrc + 4));
            store_hl(Wh, Wl, row, lc, *(const float4*)wsrc, *(const float4*)(wsrc + 4));
        }
        __syncthreads();

        // ---- 4 x k16 steps, 8 n-tile-pairs, 3-pass split mma ----
#pragma unroll
        for (int ks = 0; ks < 4; ks++) {
            uint32_t qh[4], ql[4];
            {
                const int row = w * 16 + (lane & 15);
                const int ch  = 2 * ks + (lane >> 4);
                ldsm_x4(qh, sAh + swzb(row, ch));
                ldsm_x4(ql, sAl + swzb(row, ch));
            }
#pragma unroll
            for (int tp = 0; tp < 8; tp++) {
                uint32_t kh[4], kl[4];
                const int jrow = tp * 16 + ((lane >> 4) << 3) + (lane & 7);
                const int kch  = 2 * ks + ((lane >> 3) & 1);
                ldsm_x4(kh, sWh + swzb(jrow, kch));
                ldsm_x4(kl, sWl + swzb(jrow, kch));
                mma16816(s[2 * tp],     qh, kh[0], kh[1]);
                mma16816(s[2 * tp],     qh, kl[0], kl[1]);
                mma16816(s[2 * tp],     ql, kh[0], kh[1]);
                mma16816(s[2 * tp + 1], qh, kh[2], kh[3]);
                mma16816(s[2 * tp + 1], qh, kl[2], kl[3]);
                mma16816(s[2 * tp + 1], ql, kh[2], kh[3]);
            }
        }
    }

    // ---- epilogue: bias add + store (C-fragment layout) ----
    const int row0 = bm + w * 16 + (lane >> 2);
#pragma unroll
    for (int tt = 0; tt < 16; tt++) {
        const int col = bn + tt * 8 + (lane & 3) * 2;
        const float2 bv = *(const float2*)(bias + col);
        *(float2*)(g_qproj + (size_t)row0 * NFEAT + col) =
            make_float2(s[tt][0] + bv.x, s[tt][1] + bv.y);
        *(float2*)(g_qproj + (size_t)(row0 + 8) * NFEAT + col) =
            make_float2(s[tt][2] + bv.x, s[tt][3] + bv.y);
    }
}

// ---------------------------------------------------------------------------
// Kernel 3: split-bf16 tensor-core flash attention over COMPACTED KV columns.
// X = Xh + Xl (bf16 pair); 3 mma passes per GEMM, fp32 accumulate.  S accum
// fragments re-used directly as the PV A-fragment (FA2 layout identity).
// smem 64 KB -> 2 CTAs/SM; 2 __syncthreads per KV tile.  (Audited r5+r6.)
// ---------------------------------------------------------------------------
__global__ __launch_bounds__(256, 2)
void attn_kernel(const float* __restrict__ key, const float* __restrict__ value,
                 float* __restrict__ out) {
    extern __shared__ __align__(16) unsigned char smem[];
    unsigned char* Qh = smem;              // 128*128B = 16384
    unsigned char* Ql = smem + 16384;
    unsigned char* Kh = smem + 32768;      //  64*128B =  8192
    unsigned char* Kl = smem + 40960;
    unsigned char* Vh = smem + 49152;
    unsigned char* Vl = smem + 57344;      // end 65536

    const uint32_t sQh = (uint32_t)__cvta_generic_to_shared(Qh);
    const uint32_t sQl = (uint32_t)__cvta_generic_to_shared(Ql);
    const uint32_t sKh = (uint32_t)__cvta_generic_to_shared(Kh);
    const uint32_t sKl = (uint32_t)__cvta_generic_to_shared(Kl);
    const uint32_t sVh = (uint32_t)__cvta_generic_to_shared(Vh);
    const uint32_t sVl = (uint32_t)__cvta_generic_to_shared(Vl);

    const int tid  = threadIdx.x;
    const int lane = tid & 31;
    const int w    = tid >> 5;          // warp 0..7 -> S rows 16w..16w+15
    const int blk  = blockIdx.x;
    const int qt = blk & 15;            // T1/BQ = 16
    const int h  = (blk >> 4) & 15;
    const int b  = blk >> 8;
    const int q0 = qt * BQ;

    const int cnt = g_valid_cnt[b];
    const float* kbase = key   + (size_t)b * T2 * NFEAT + h * DK;
    const float* vbase = value + (size_t)b * T2 * NFEAT + h * DK;
    const int* vidx = g_valid_idx + b * T2;
    float* outbase = out + (size_t)(b * T1 + q0) * NFEAT + h * DK;

    if (cnt == 0) {   // fully masked batch: reference output is exactly zero
        const float4 z = make_float4(0.f, 0.f, 0.f, 0.f);
#pragma unroll
        for (int p = 0; p < 8; p++) {
            const int idx = tid + p * 256;        // 128 rows x 16 f4 chunks
            *(float4*)(outbase + (size_t)(idx >> 4) * NFEAT + (idx & 15) * 4) = z;
        }
        return;
    }

    // ---- convert Q tile (fp32 -> bf16 hi/lo, swizzled); 1024 chunks ----
#pragma unroll
    for (int p = 0; p < 4; p++) {
        const int idx = tid + p * 256;
        const int row = idx >> 3, c = idx & 7;
        const float* src = g_qproj + (size_t)(b * T1 + q0 + row) * NFEAT + h * DK + c * 8;
        store_hl(Qh, Ql, row, c, *(const float4*)src, *(const float4*)(src + 4));
    }

    float s[8][4], o[8][4];
    float m0 = -INFINITY, m1 = -INFINITY, l0 = 0.f, l1 = 0.f;
#pragma unroll
    for (int tt = 0; tt < 8; tt++)
#pragma unroll
        for (int r = 0; r < 4; r++) o[tt][r] = 0.f;

    const int ntiles = (cnt + BK - 1) / BK;
    for (int t = 0; t < ntiles; t++) {
        const int kv0 = t * BK;
        __syncthreads();   // prior tile's K/V consumed (covers Q stores at t=0)

        // ---- gather + convert K and V (512 chunks each); prefetch next ----
#pragma unroll
        for (int p = 0; p < 2; p++) {
            const int idx = tid + p * 256;
            const int row = idx >> 3, c = idx & 7;
            const int jg = kv0 + row;
            const int grow = vidx[(jg < cnt) ? jg : 0];
            const float* ksrc = kbase + (size_t)grow * NFEAT + c * 8;
            const float* vsrc = vbase + (size_t)grow * NFEAT + c * 8;
            const float4 k0 = *(const float4*)ksrc, k1 = *(const float4*)(ksrc + 4);
            const float4 v0 = *(const float4*)vsrc, v1 = *(const float4*)(vsrc + 4);
            const int jn = jg + BK;
            if (jn < cnt) {
                const int nr = vidx[jn];
                prefetch_l2(kbase + (size_t)nr * NFEAT + c * 8);
                prefetch_l2(vbase + (size_t)nr * NFEAT + c * 8);
            }
            store_hl(Kh, Kl, row, c, k0, k1);
            store_hl(Vh, Vl, row, c, v0, v1);
        }
        __syncthreads();

        // ---- S = Q K^T : 3-pass split mma, fp32 accum ----
#pragma unroll
        for (int tt = 0; tt < 8; tt++)
#pragma unroll
            for (int r = 0; r < 4; r++) s[tt][r] = 0.f;

        const int r0 = w * 16;
#pragma unroll
        for (int ks = 0; ks < 4; ks++) {
            uint32_t qh[4], ql[4];
            {
                const int row = r0 + (lane & 15);
                const int ch  = 2 * ks + (lane >> 4);
                ldsm_x4(qh, sQh + swzb(row, ch));
                ldsm_x4(ql, sQl + swzb(row, ch));
            }
#pragma unroll
            for (int tp = 0; tp < 4; tp++) {
                uint32_t kh[4], kl[4];
                const int jrow = tp * 16 + ((lane >> 4) << 3) + (lane & 7);
                const int kch  = 2 * ks + ((lane >> 3) & 1);
                ldsm_x4(kh, sKh + swzb(jrow, kch));
                ldsm_x4(kl, sKl + swzb(jrow, kch));
                mma16816(s[2 * tp],     qh, kh[0], kh[1]);
                mma16816(s[2 * tp],     qh, kl[0], kl[1]);
                mma16816(s[2 * tp],     ql, kh[0], kh[1]);
                mma16816(s[2 * tp + 1], qh, kh[2], kh[3]);
                mma16816(s[2 * tp + 1], qh, kl[2], kl[3]);
                mma16816(s[2 * tp + 1], ql, kh[2], kh[3]);
            }
        }

        // ---- scale, tail-mask, online softmax (quad-wide rows) ----
        const int cb = (lane & 3) * 2;
#pragma unroll
        for (int tt = 0; tt < 8; tt++) {
            const int j0 = kv0 + tt * 8 + cb;
            s[tt][0] = (j0     < cnt) ? s[tt][0] * 0.125f : -INFINITY;
            s[tt][1] = (j0 + 1 < cnt) ? s[tt][1] * 0.125f : -INFINITY;
            s[tt][2] = (j0     < cnt) ? s[tt][2] * 0.125f : -INFINITY;
            s[tt][3] = (j0 + 1 < cnt) ? s[tt][3] * 0.125f : -INFINITY;
        }
        float v0 = -INFINITY, v1 = -INFINITY;
#pragma unroll
        for (int tt = 0; tt < 8; tt++) {
            v0 = fmaxf(v0, fmaxf(s[tt][0], s[tt][1]));
            v1 = fmaxf(v1, fmaxf(s[tt][2], s[tt][3]));
        }
        v0 = fmaxf(v0, __shfl_xor_sync(0xffffffffu, v0, 1));
        v0 = fmaxf(v0, __shfl_xor_sync(0xffffffffu, v0, 2));
        v1 = fmaxf(v1, __shfl_xor_sync(0xffffffffu, v1, 1));
        v1 = fmaxf(v1, __shfl_xor_sync(0xffffffffu, v1, 2));
        const float mn0 = fmaxf(m0, v0), mn1 = fmaxf(m1, v1);
        const float corr0 = __expf(m0 - mn0), corr1 = __expf(m1 - mn1);
        m0 = mn0; m1 = mn1;
        float rs0 = 0.f, rs1 = 0.f;
#pragma unroll
        for (int tt = 0; tt < 8; tt++) {
            s[tt][0] = __expf(s[tt][0] - mn0);   // masked -> exactly 0
            s[tt][1] = __expf(s[tt][1] - mn0);
            s[tt][2] = __expf(s[tt][2] - mn1);
            s[tt][3] = __expf(s[tt][3] - mn1);
            rs0 += s[tt][0] + s[tt][1];
            rs1 += s[tt][2] + s[tt][3];
        }
        rs0 += __shfl_xor_sync(0xffffffffu, rs0, 1);
        rs0 += __shfl_xor_sync(0xffffffffu, rs0, 2);
        rs1 += __shfl_xor_sync(0xffffffffu, rs1, 1);
        rs1 += __shfl_xor_sync(0xffffffffu, rs1, 2);
        l0 = l0 * corr0 + rs0;
        l1 = l1 * corr1 + rs1;
#pragma unroll
        for (int tt = 0; tt < 8; tt++) {
            o[tt][0] *= corr0; o[tt][1] *= corr0;
            o[tt][2] *= corr1; o[tt][3] *= corr1;
        }

        // ---- O += P V : P fragments built in-register from S accum ----
#pragma unroll
        for (int ks = 0; ks < 4; ks++) {
            uint32_t vh0[4], vl0[4];
            {
                const int vrow = ks * 16 + (((lane >> 3) & 1) << 3) + (lane & 7);
                ldsm_x4_t(vh0, sVh + swzb(vrow, (lane >> 4)));
                ldsm_x4_t(vl0, sVl + swzb(vrow, (lane >> 4)));
            }
            uint32_t aH[4], aL[4];
            aH[0] = pack_bf16(s[2 * ks][0], s[2 * ks][1]);
            aH[1] = pack_bf16(s[2 * ks][2], s[2 * ks][3]);
            aH[2] = pack_bf16(s[2 * ks + 1][0], s[2 * ks + 1][1]);
            aH[3] = pack_bf16(s[2 * ks + 1][2], s[2 * ks + 1][3]);
            aL[0] = pack_bf16(bf16_res(s[2 * ks][0]), bf16_res(s[2 * ks][1]));
            aL[1] = pack_bf16(bf16_res(s[2 * ks][2]), bf16_res(s[2 * ks][3]));
            aL[2] = pack_bf16(bf16_res(s[2 * ks + 1][0]), bf16_res(s[2 * ks + 1][1]));
            aL[3] = pack_bf16(bf16_res(s[2 * ks + 1][2]), bf16_res(s[2 * ks + 1][3]));
            mma16816(o[0], aH, vh0[0], vh0[1]);
            mma16816(o[0], aH, vl0[0], vl0[1]);
            mma16816(o[0], aL, vh0[0], vh0[1]);
            mma16816(o[1], aH, vh0[2], vh0[3]);
            mma16816(o[1], aH, vl0[2], vl0[3]);
            mma16816(o[1], aL, vh0[2], vh0[3]);
#pragma unroll
            for (int tp = 1; tp < 4; tp++) {
                uint32_t vh[4], vl[4];
                const int vrow = ks * 16 + (((lane >> 3) & 1) << 3) + (lane & 7);
                const int vch  = 2 * tp + (lane >> 4);
                ldsm_x4_t(vh, sVh + swzb(vrow, vch));
                ldsm_x4_t(vl, sVl + swzb(vrow, vch));
                mma16816(o[2 * tp],     aH, vh[0], vh[1]);
                mma16816(o[2 * tp],     aH, vl[0], vl[1]);
                mma16816(o[2 * tp],     aL, vh[0], vh[1]);
                mma16816(o[2 * tp + 1], aH, vh[2], vh[3]);
                mma16816(o[2 * tp + 1], aH, vl[2], vl[3]);
                mma16816(o[2 * tp + 1], aL, vh[2], vh[3]);
            }
        }
    }

    // ---- normalize and store (rows w*16+lane/4 and +8; cols per C layout) ----
    const int row0 = w * 16 + (lane >> 2);
    const float inv0 = 1.0f / l0, inv1 = 1.0f / l1;
#pragma unroll
    for (int tt = 0; tt < 8; tt++) {
        const int col = tt * 8 + (lane & 3) * 2;
        *(float2*)(outbase + (size_t)row0 * NFEAT + col) =
            make_float2(o[tt][0] * inv0, o[tt][1] * inv0);
        *(float2*)(outbase + (size_t)(row0 + 8) * NFEAT + col) =
            make_float2(o[tt][2] * inv1, o[tt][3] * inv1);
    }
}

// ---------------------------------------------------------------------------
// Entry point.  Inputs per metadata order: query, key, value, mask, Wq, bq.
// ---------------------------------------------------------------------------
extern "C" void kernel_launch(void* const* d_in, const int* in_sizes, int n_in,
                              void* d_out, int out_size) {
    const float* query = (const float*)d_in[0];
    const float* key   = (const float*)d_in[1];
    const float* value = (const float*)d_in[2];
    const int*   mask  = (const int*)  d_in[3];
    const float* Wq    = (const float*)d_in[4];
    const float* bq    = (const float*)d_in[5];
    float* out = (float*)d_out;

    // >48KB dynamic smem opt-in (host attribute; idempotent; capture-legal).
    cudaFuncSetAttribute(attn_kernel,
                         cudaFuncAttributeMaxDynamicSharedMemorySize,
                         ATTN_SMEM_BYTES);
    cudaFuncSetAttribute(qproj_kernel,
                         cudaFuncAttributeMaxDynamicSharedMemorySize,
                         QPROJ_SMEM_BYTES);

    compact_mask_kernel<<<BATCH, 32>>>(mask);
    qproj_kernel<<<dim3(NFEAT / 128, (BATCH * T1) / 128), 256, QPROJ_SMEM_BYTES>>>(query, Wq, bq);
    attn_kernel<<<BATCH * NH * (T1 / BQ), 256, ATTN_SMEM_BYTES>>>(key, value, out);
}

// round 9
// speedup vs baseline: 2.6139x; 1.0835x over previous
#include <cuda_runtime.h>
#include <cuda_bf16.h>
#include <math.h>
#include <stdint.h>

// Shapes fixed by the problem definition.
#define BATCH 4
#define T1    2048
#define T2    2048
#define NFEAT 1024
#define NH    16
#define DK    64

// Attention tiling: BQ=128 rows (8 warps x 16), BK=64 kv cols, 256 threads.
#define BQ    128
#define BK    64

// attn smem: Qh,Ql[128][64] + 2 stages x {Kh,Kl,Vh,Vl}[64][64] bf16 = 96 KB
#define SM_QH        0
#define SM_QL        16384
#define SM_STAGE(s)  (32768 + (s) * 32768)
#define ST_KH        0
#define ST_KL        8192
#define ST_VH        16384
#define ST_VL        24576
#define ATTN_SMEM_BYTES  98304
#define QPROJ_SMEM_BYTES 65536   // Ah,Al,Wh,Wl [128][64] bf16

// Scratch (no dynamic allocation allowed).  All bf16 split pairs.
__device__ __nv_bfloat16 g_ah[BATCH * T1 * NFEAT];   // query hi/lo
__device__ __nv_bfloat16 g_al[BATCH * T1 * NFEAT];
__device__ __nv_bfloat16 g_wh[NFEAT * NFEAT];        // Wq hi/lo
__device__ __nv_bfloat16 g_wl[NFEAT * NFEAT];
__device__ __nv_bfloat16 g_qh[BATCH * T1 * NFEAT];   // projected Q hi/lo
__device__ __nv_bfloat16 g_ql[BATCH * T1 * NFEAT];
__device__ __nv_bfloat16 g_kh[BATCH * T2 * NFEAT];   // compacted K/V hi/lo
__device__ __nv_bfloat16 g_kl[BATCH * T2 * NFEAT];
__device__ __nv_bfloat16 g_vh[BATCH * T2 * NFEAT];
__device__ __nv_bfloat16 g_vl[BATCH * T2 * NFEAT];
__device__ int g_valid_idx[BATCH * T2];
__device__ int g_valid_cnt[BATCH];

__device__ __forceinline__ void prefetch_l2(const void* p) {
    asm volatile("prefetch.global.L2 [%0];" :: "l"(p));
}

// ---- bf16 split helpers -------------------------------------------------
__device__ __forceinline__ uint32_t pack_bf16(float x, float y) {
    __nv_bfloat162 t = __floats2bfloat162_rn(x, y);   // .x = x (low 16 bits)
    return *reinterpret_cast<uint32_t*>(&t);
}
__device__ __forceinline__ float bf16_res(float x) {
    return x - __bfloat162float(__float2bfloat16_rn(x));
}

// ---- smem swizzle: row-major [row][64] bf16, 8 x 16B chunks per 128B row.
__device__ __forceinline__ uint32_t swzb(int row, int ch) {
    return (uint32_t)(row * 128 + (((ch) ^ (row & 7)) << 4));
}

// ---- cp.async -----------------------------------------------------------
__device__ __forceinline__ void cp16(uint32_t dst, const void* src) {
    asm volatile("cp.async.cg.shared.global [%0], [%1], 16;" :: "r"(dst), "l"(src) : "memory");
}
__device__ __forceinline__ void cp_commit() {
    asm volatile("cp.async.commit_group;" ::: "memory");
}
__device__ __forceinline__ void cp_wait0() { asm volatile("cp.async.wait_group 0;" ::: "memory"); }
__device__ __forceinline__ void cp_wait1() { asm volatile("cp.async.wait_group 1;" ::: "memory"); }

// ---- tensor-core wrappers ----------------------------------------------
__device__ __forceinline__ void ldsm_x4(uint32_t* r, uint32_t addr) {
    asm volatile("ldmatrix.sync.aligned.m8n8.x4.shared.b16 {%0,%1,%2,%3}, [%4];"
        : "=r"(r[0]), "=r"(r[1]), "=r"(r[2]), "=r"(r[3]) : "r"(addr));
}
__device__ __forceinline__ void ldsm_x4_t(uint32_t* r, uint32_t addr) {
    asm volatile("ldmatrix.sync.aligned.m8n8.x4.trans.shared.b16 {%0,%1,%2,%3}, [%4];"
        : "=r"(r[0]), "=r"(r[1]), "=r"(r[2]), "=r"(r[3]) : "r"(addr));
}
__device__ __forceinline__ void mma16816(float* c, const uint32_t* a, uint32_t b0, uint32_t b1) {
    asm volatile("mma.sync.aligned.m16n8k16.row.col.f32.bf16.bf16.f32 "
        "{%0,%1,%2,%3}, {%4,%5,%6,%7}, {%8,%9}, {%0,%1,%2,%3};"
        : "+f"(c[0]), "+f"(c[1]), "+f"(c[2]), "+f"(c[3])
        : "r"(a[0]), "r"(a[1]), "r"(a[2]), "r"(a[3]), "r"(b0), "r"(b1));
}

// ---------------------------------------------------------------------------
// Kernel 1: per-batch compaction of valid (mask != 0) column indices.
// ---------------------------------------------------------------------------
__global__ void compact_mask_kernel(const int* __restrict__ mask) {
    const int b = blockIdx.x;
    const int lane = threadIdx.x;
    const int* m = mask + b * T2;
    int cnt = 0;
    for (int base = 0; base < T2; base += 32) {
        const int v = m[base + lane];
        const unsigned bal = __ballot_sync(0xffffffffu, v != 0);
        if (v)
            g_valid_idx[b * T2 + cnt + __popc(bal & ((1u << lane) - 1u))] = base + lane;
        cnt += __popc(bal);
    }
    if (lane == 0) g_valid_cnt[b] = cnt;
}

// ---------------------------------------------------------------------------
// Prepass A: elementwise fp32 -> (hi, lo) bf16 split.
// ---------------------------------------------------------------------------
__global__ void split_kernel(const float* __restrict__ src,
                             __nv_bfloat16* __restrict__ dh,
                             __nv_bfloat16* __restrict__ dl, int n4) {
    const int i = blockIdx.x * blockDim.x + threadIdx.x;
    if (i >= n4) return;
    const float4 f = ((const float4*)src)[i];
    uint2 hh, ll;
    hh.x = pack_bf16(f.x, f.y); hh.y = pack_bf16(f.z, f.w);
    ll.x = pack_bf16(bf16_res(f.x), bf16_res(f.y));
    ll.y = pack_bf16(bf16_res(f.z), bf16_res(f.w));
    ((uint2*)dh)[i] = hh;
    ((uint2*)dl)[i] = ll;
}

// ---------------------------------------------------------------------------
// Prepass B: gather-compact K/V rows by valid index, split to bf16 hi/lo.
// Rows >= cnt are zero-filled (masked tail: P=0 x V=0 in the attention PV).
// Grid (T2, BATCH), 256 threads, 4 elements each.
// ---------------------------------------------------------------------------
__global__ void kv_split_kernel(const float* __restrict__ key,
                                const float* __restrict__ value) {
    const int j = blockIdx.x, b = blockIdx.y, t = threadIdx.x;
    const int cnt = g_valid_cnt[b];
    const size_t dst = ((size_t)b * T2 + j) * NFEAT + t * 4;
    if (j < cnt) {
        const int row = g_valid_idx[b * T2 + j];
        const size_t src = ((size_t)b * T2 + row) * NFEAT + t * 4;
        const float4 k = *(const float4*)(key + src);
        const float4 v = *(const float4*)(value + src);
        uint2 u;
        u.x = pack_bf16(k.x, k.y); u.y = pack_bf16(k.z, k.w);
        *(uint2*)&g_kh[dst] = u;
        u.x = pack_bf16(bf16_res(k.x), bf16_res(k.y));
        u.y = pack_bf16(bf16_res(k.z), bf16_res(k.w));
        *(uint2*)&g_kl[dst] = u;
        u.x = pack_bf16(v.x, v.y); u.y = pack_bf16(v.z, v.w);
        *(uint2*)&g_vh[dst] = u;
        u.x = pack_bf16(bf16_res(v.x), bf16_res(v.y));
        u.y = pack_bf16(bf16_res(v.z), bf16_res(v.w));
        *(uint2*)&g_vl[dst] = u;
    } else {
        const uint2 z = make_uint2(0u, 0u);
        *(uint2*)&g_kh[dst] = z;
        *(uint2*)&g_kl[dst] = z;
        *(uint2*)&g_vh[dst] = z;
        *(uint2*)&g_vl[dst] = z;
    }
}

// ---------------------------------------------------------------------------
// Kernel 2: Q projection GEMM on tensor cores (split-bf16, 3-pass).
// Loads pre-split bf16 A/W (no in-kernel conversion); writes Q pre-split.
// ---------------------------------------------------------------------------
__global__ __launch_bounds__(256, 2)
void qproj_kernel(const float* __restrict__ bias) {
    extern __shared__ __align__(16) unsigned char qsm[];
    unsigned char* Ah = qsm;               // 128*128B = 16384
    unsigned char* Al = qsm + 16384;
    unsigned char* Wh = qsm + 32768;
    unsigned char* Wl = qsm + 49152;       // end 65536

    const uint32_t sAh = (uint32_t)__cvta_generic_to_shared(Ah);
    const uint32_t sAl = (uint32_t)__cvta_generic_to_shared(Al);
    const uint32_t sWh = (uint32_t)__cvta_generic_to_shared(Wh);
    const uint32_t sWl = (uint32_t)__cvta_generic_to_shared(Wl);

    const int tid  = threadIdx.x;
    const int lane = tid & 31;
    const int w    = tid >> 5;
    const int bm   = blockIdx.y * 128;
    const int bn   = blockIdx.x * 128;

    float s[16][4];
#pragma unroll
    for (int tt = 0; tt < 16; tt++)
#pragma unroll
        for (int r = 0; r < 4; r++) s[tt][r] = 0.f;

    const int lrow = tid >> 3;       // 0..31 (+p*32)
    const int lc   = tid & 7;        // 16B chunk

    for (int kc = 0; kc < NFEAT / 64; kc++) {
        const int k0 = kc * 64;
        __syncthreads();   // previous chunk consumed
#pragma unroll
        for (int p = 0; p < 4; p++) {
            const int row = lrow + p * 32;
            const size_t aoff = (size_t)(bm + row) * NFEAT + k0 + lc * 8;
            const size_t woff = (size_t)(bn + row) * NFEAT + k0 + lc * 8;
            if (kc + 1 < NFEAT / 64) {
                prefetch_l2(&g_ah[aoff + 64]);
                prefetch_l2(&g_wh[woff + 64]);
            }
            const uint32_t sw = swzb(row, lc);
            *(uint4*)(Ah + sw) = *(const uint4*)&g_ah[aoff];
            *(uint4*)(Al + sw) = *(const uint4*)&g_al[aoff];
            *(uint4*)(Wh + sw) = *(const uint4*)&g_wh[woff];
            *(uint4*)(Wl + sw) = *(const uint4*)&g_wl[woff];
        }
        __syncthreads();

#pragma unroll
        for (int ks = 0; ks < 4; ks++) {
            uint32_t qh[4], ql[4];
            {
                const int row = w * 16 + (lane & 15);
                const int ch  = 2 * ks + (lane >> 4);
                ldsm_x4(qh, sAh + swzb(row, ch));
                ldsm_x4(ql, sAl + swzb(row, ch));
            }
#pragma unroll
            for (int tp = 0; tp < 8; tp++) {
                uint32_t kh[4], kl[4];
                const int jrow = tp * 16 + ((lane >> 4) << 3) + (lane & 7);
                const int kch  = 2 * ks + ((lane >> 3) & 1);
                ldsm_x4(kh, sWh + swzb(jrow, kch));
                ldsm_x4(kl, sWl + swzb(jrow, kch));
                mma16816(s[2 * tp],     qh, kh[0], kh[1]);
                mma16816(s[2 * tp],     qh, kl[0], kl[1]);
                mma16816(s[2 * tp],     ql, kh[0], kh[1]);
                mma16816(s[2 * tp + 1], qh, kh[2], kh[3]);
                mma16816(s[2 * tp + 1], qh, kl[2], kl[3]);
                mma16816(s[2 * tp + 1], ql, kh[2], kh[3]);
            }
        }
    }

    // ---- epilogue: bias add in fp32, split to bf16 hi/lo, store ----
    const int row0 = bm + w * 16 + (lane >> 2);
#pragma unroll
    for (int tt = 0; tt < 16; tt++) {
        const int col = bn + tt * 8 + (lane & 3) * 2;
        const float2 bv = *(const float2*)(bias + col);
        const float x0 = s[tt][0] + bv.x, x1 = s[tt][1] + bv.y;
        const float x2 = s[tt][2] + bv.x, x3 = s[tt][3] + bv.y;
        const size_t o0 = (size_t)row0 * NFEAT + col;
        const size_t o1 = (size_t)(row0 + 8) * NFEAT + col;
        *(uint32_t*)&g_qh[o0] = pack_bf16(x0, x1);
        *(uint32_t*)&g_ql[o0] = pack_bf16(bf16_res(x0), bf16_res(x1));
        *(uint32_t*)&g_qh[o1] = pack_bf16(x2, x3);
        *(uint32_t*)&g_ql[o1] = pack_bf16(bf16_res(x2), bf16_res(x3));
    }
}

// ---------------------------------------------------------------------------
// Kernel 3: split-bf16 tensor-core flash attention, cp.async 2-stage pipeline
// over pre-compacted pre-split K/V (contiguous loads, no gather, no convert).
// S accumulator fragments re-used as PV A-fragments (audited FA2 identity).
// ---------------------------------------------------------------------------
__global__ __launch_bounds__(256, 2)
void attn_kernel(float* __restrict__ out) {
    extern __shared__ __align__(16) unsigned char smem[];
    const uint32_t sbase = (uint32_t)__cvta_generic_to_shared(smem);

    const int tid  = threadIdx.x;
    const int lane = tid & 31;
    const int w    = tid >> 5;          // warp 0..7 -> S rows 16w..16w+15
    const int blk  = blockIdx.x;
    const int qt = blk & 15;            // T1/BQ = 16
    const int h  = (blk >> 4) & 15;
    const int b  = blk >> 8;
    const int q0 = qt * BQ;

    const int cnt = g_valid_cnt[b];
    float* outbase = out + (size_t)(b * T1 + q0) * NFEAT + h * DK;

    if (cnt == 0) {   // fully masked batch: exact zeros
        const float4 z = make_float4(0.f, 0.f, 0.f, 0.f);
#pragma unroll
        for (int p = 0; p < 8; p++) {
            const int idx = tid + p * 256;
            *(float4*)(outbase + (size_t)(idx >> 4) * NFEAT + (idx & 15) * 4) = z;
        }
        return;
    }

    const size_t kvbase = (size_t)b * T2 * NFEAT + h * DK;
    const int ntiles = (cnt + BK - 1) / BK;

    // ---- issue Q (8 cp) + stage 0 K/V (8 cp), one commit group ----
#pragma unroll
    for (int p = 0; p < 4; p++) {
        const int idx = tid + p * 256;
        const int row = idx >> 3, c = idx & 7;
        const size_t off = (size_t)(b * T1 + q0 + row) * NFEAT + h * DK + c * 8;
        cp16(sbase + SM_QH + swzb(row, c), &g_qh[off]);
        cp16(sbase + SM_QL + swzb(row, c), &g_ql[off]);
    }
#pragma unroll
    for (int p = 0; p < 2; p++) {
        const int idx = tid + p * 256;
        const int row = idx >> 3, c = idx & 7;
        const size_t off = kvbase + (size_t)row * NFEAT + c * 8;
        const uint32_t sw = swzb(row, c);
        const uint32_t st = sbase + SM_STAGE(0);
        cp16(st + ST_KH + sw, &g_kh[off]);
        cp16(st + ST_KL + sw, &g_kl[off]);
        cp16(st + ST_VH + sw, &g_vh[off]);
        cp16(st + ST_VL + sw, &g_vl[off]);
    }
    cp_commit();

    float s[8][4], o[8][4];
    float m0 = -INFINITY, m1 = -INFINITY, l0 = 0.f, l1 = 0.f;
#pragma unroll
    for (int tt = 0; tt < 8; tt++)
#pragma unroll
        for (int r = 0; r < 4; r++) o[tt][r] = 0.f;

    for (int t = 0; t < ntiles; t++) {
        const int kv0 = t * BK;
        // ---- issue next stage while current loads finish ----
        if (t + 1 < ntiles) {
#pragma unroll
            for (int p = 0; p < 2; p++) {
                const int idx = tid + p * 256;
                const int row = idx >> 3, c = idx & 7;
                const size_t off = kvbase + (size_t)(kv0 + BK + row) * NFEAT + c * 8;
                const uint32_t sw = swzb(row, c);
                const uint32_t st = sbase + SM_STAGE((t + 1) & 1);
                cp16(st + ST_KH + sw, &g_kh[off]);
                cp16(st + ST_KL + sw, &g_kl[off]);
                cp16(st + ST_VH + sw, &g_vh[off]);
                cp16(st + ST_VL + sw, &g_vl[off]);
            }
            cp_commit();
            cp_wait1();
        } else {
            cp_wait0();
        }
        __syncthreads();

        const uint32_t st = sbase + SM_STAGE(t & 1);
        const uint32_t sKh = st + ST_KH, sKl = st + ST_KL;
        const uint32_t sVh = st + ST_VH, sVl = st + ST_VL;

        // ---- S = Q K^T : 3-pass split mma, fp32 accum ----
#pragma unroll
        for (int tt = 0; tt < 8; tt++)
#pragma unroll
            for (int r = 0; r < 4; r++) s[tt][r] = 0.f;

        const int r0 = w * 16;
#pragma unroll
        for (int ks = 0; ks < 4; ks++) {
            uint32_t qh[4], ql[4];
            {
                const int row = r0 + (lane & 15);
                const int ch  = 2 * ks + (lane >> 4);
                ldsm_x4(qh, sbase + SM_QH + swzb(row, ch));
                ldsm_x4(ql, sbase + SM_QL + swzb(row, ch));
            }
#pragma unroll
            for (int tp = 0; tp < 4; tp++) {
                uint32_t kh[4], kl[4];
                const int jrow = tp * 16 + ((lane >> 4) << 3) + (lane & 7);
                const int kch  = 2 * ks + ((lane >> 3) & 1);
                ldsm_x4(kh, sKh + swzb(jrow, kch));
                ldsm_x4(kl, sKl + swzb(jrow, kch));
                mma16816(s[2 * tp],     qh, kh[0], kh[1]);
                mma16816(s[2 * tp],     qh, kl[0], kl[1]);
                mma16816(s[2 * tp],     ql, kh[0], kh[1]);
                mma16816(s[2 * tp + 1], qh, kh[2], kh[3]);
                mma16816(s[2 * tp + 1], qh, kl[2], kl[3]);
                mma16816(s[2 * tp + 1], ql, kh[2], kh[3]);
            }
        }

        // ---- scale, tail-mask, online softmax (quad-wide rows) ----
        const int cb = (lane & 3) * 2;
#pragma unroll
        for (int tt = 0; tt < 8; tt++) {
            const int j0 = kv0 + tt * 8 + cb;
            s[tt][0] = (j0     < cnt) ? s[tt][0] * 0.125f : -INFINITY;
            s[tt][1] = (j0 + 1 < cnt) ? s[tt][1] * 0.125f : -INFINITY;
            s[tt][2] = (j0     < cnt) ? s[tt][2] * 0.125f : -INFINITY;
            s[tt][3] = (j0 + 1 < cnt) ? s[tt][3] * 0.125f : -INFINITY;
        }
        float v0 = -INFINITY, v1 = -INFINITY;
#pragma unroll
        for (int tt = 0; tt < 8; tt++) {
            v0 = fmaxf(v0, fmaxf(s[tt][0], s[tt][1]));
            v1 = fmaxf(v1, fmaxf(s[tt][2], s[tt][3]));
        }
        v0 = fmaxf(v0, __shfl_xor_sync(0xffffffffu, v0, 1));
        v0 = fmaxf(v0, __shfl_xor_sync(0xffffffffu, v0, 2));
        v1 = fmaxf(v1, __shfl_xor_sync(0xffffffffu, v1, 1));
        v1 = fmaxf(v1, __shfl_xor_sync(0xffffffffu, v1, 2));
        const float mn0 = fmaxf(m0, v0), mn1 = fmaxf(m1, v1);
        const float corr0 = __expf(m0 - mn0), corr1 = __expf(m1 - mn1);
        m0 = mn0; m1 = mn1;
        float rs0 = 0.f, rs1 = 0.f;
#pragma unroll
        for (int tt = 0; tt < 8; tt++) {
            s[tt][0] = __expf(s[tt][0] - mn0);   // masked -> exactly 0
            s[tt][1] = __expf(s[tt][1] - mn0);
            s[tt][2] = __expf(s[tt][2] - mn1);
            s[tt][3] = __expf(s[tt][3] - mn1);
            rs0 += s[tt][0] + s[tt][1];
            rs1 += s[tt][2] + s[tt][3];
        }
        rs0 += __shfl_xor_sync(0xffffffffu, rs0, 1);
        rs0 += __shfl_xor_sync(0xffffffffu, rs0, 2);
        rs1 += __shfl_xor_sync(0xffffffffu, rs1, 1);
        rs1 += __shfl_xor_sync(0xffffffffu, rs1, 2);
        l0 = l0 * corr0 + rs0;
        l1 = l1 * corr1 + rs1;
#pragma unroll
        for (int tt = 0; tt < 8; tt++) {
            o[tt][0] *= corr0; o[tt][1] *= corr0;
            o[tt][2] *= corr1; o[tt][3] *= corr1;
        }

        // ---- O += P V : P fragments built in-register from S accum ----
#pragma unroll
        for (int ks = 0; ks < 4; ks++) {
            uint32_t aH[4], aL[4];
            aH[0] = pack_bf16(s[2 * ks][0], s[2 * ks][1]);
            aH[1] = pack_bf16(s[2 * ks][2], s[2 * ks][3]);
            aH[2] = pack_bf16(s[2 * ks + 1][0], s[2 * ks + 1][1]);
            aH[3] = pack_bf16(s[2 * ks + 1][2], s[2 * ks + 1][3]);
            aL[0] = pack_bf16(bf16_res(s[2 * ks][0]), bf16_res(s[2 * ks][1]));
            aL[1] = pack_bf16(bf16_res(s[2 * ks][2]), bf16_res(s[2 * ks][3]));
            aL[2] = pack_bf16(bf16_res(s[2 * ks + 1][0]), bf16_res(s[2 * ks + 1][1]));
            aL[3] = pack_bf16(bf16_res(s[2 * ks + 1][2]), bf16_res(s[2 * ks + 1][3]));
#pragma unroll
            for (int tp = 0; tp < 4; tp++) {
                uint32_t vh[4], vl[4];
                const int vrow = ks * 16 + (((lane >> 3) & 1) << 3) + (lane & 7);
                const int vch  = 2 * tp + (lane >> 4);
                ldsm_x4_t(vh, sVh + swzb(vrow, vch));
                ldsm_x4_t(vl, sVl + swzb(vrow, vch));
                mma16816(o[2 * tp],     aH, vh[0], vh[1]);
                mma16816(o[2 * tp],     aH, vl[0], vl[1]);
                mma16816(o[2 * tp],     aL, vh[0], vh[1]);
                mma16816(o[2 * tp + 1], aH, vh[2], vh[3]);
                mma16816(o[2 * tp + 1], aH, vl[2], vl[3]);
                mma16816(o[2 * tp + 1], aL, vh[2], vh[3]);
            }
        }
        __syncthreads();   // all warps done reading stage t&1 before re-issue
    }

    // ---- normalize and store ----
    const int row0 = w * 16 + (lane >> 2);
    const float inv0 = 1.0f / l0, inv1 = 1.0f / l1;
#pragma unroll
    for (int tt = 0; tt < 8; tt++) {
        const int col = tt * 8 + (lane & 3) * 2;
        *(float2*)(outbase + (size_t)row0 * NFEAT + col) =
            make_float2(o[tt][0] * inv0, o[tt][1] * inv0);
        *(float2*)(outbase + (size_t)(row0 + 8) * NFEAT + col) =
            make_float2(o[tt][2] * inv1, o[tt][3] * inv1);
    }
}

// ---------------------------------------------------------------------------
// Entry point.  Inputs per metadata order: query, key, value, mask, Wq, bq.
// ---------------------------------------------------------------------------
extern "C" void kernel_launch(void* const* d_in, const int* in_sizes, int n_in,
                              void* d_out, int out_size) {
    const float* query = (const float*)d_in[0];
    const float* key   = (const float*)d_in[1];
    const float* value = (const float*)d_in[2];
    const int*   mask  = (const int*)  d_in[3];
    const float* Wq    = (const float*)d_in[4];
    const float* bq    = (const float*)d_in[5];
    float* out = (float*)d_out;

    __nv_bfloat16 *p_ah, *p_al, *p_wh, *p_wl;
    cudaGetSymbolAddress((void**)&p_ah, g_ah);
    cudaGetSymbolAddress((void**)&p_al, g_al);
    cudaGetSymbolAddress((void**)&p_wh, g_wh);
    cudaGetSymbolAddress((void**)&p_wl, g_wl);

    cudaFuncSetAttribute(attn_kernel,
                         cudaFuncAttributeMaxDynamicSharedMemorySize,
                         ATTN_SMEM_BYTES);
    cudaFuncSetAttribute(qproj_kernel,
                         cudaFuncAttributeMaxDynamicSharedMemorySize,
                         QPROJ_SMEM_BYTES);

    compact_mask_kernel<<<BATCH, 32>>>(mask);
    {
        const int nA4 = BATCH * T1 * NFEAT / 4;
        split_kernel<<<(nA4 + 255) / 256, 256>>>(query, p_ah, p_al, nA4);
        const int nW4 = NFEAT * NFEAT / 4;
        split_kernel<<<(nW4 + 255) / 256, 256>>>(Wq, p_wh, p_wl, nW4);
    }
    kv_split_kernel<<<dim3(T2, BATCH), 256>>>(key, value);
    qproj_kernel<<<dim3(NFEAT / 128, (BATCH * T1) / 128), 256, QPROJ_SMEM_BYTES>>>(bq);
    attn_kernel<<<BATCH * NH * (T1 / BQ), 256, ATTN_SMEM_BYTES>>>(out);
}

// round 17
// speedup vs baseline: 2.7100x; 1.0368x over previous
#include <cuda_runtime.h>
#include <cuda_bf16.h>
#include <math.h>
#include <stdint.h>

// Shapes fixed by the problem definition.
#define BATCH 4
#define T1    2048
#define T2    2048
#define NFEAT 1024
#define NH    16
#define DK    64

// Attention tiling: BQ=128 rows (8 warps x 16), BK=64 kv cols, 256 threads.
#define BQ    128
#define BK    64

// attn smem: Qh,Ql[128][64] + 2 stages x {Kh,Kl,Vh,Vl}[64][64] bf16 = 96 KB
#define SM_QH        0
#define SM_QL        16384
#define SM_STAGE(s)  (32768 + (s) * 32768)
#define ST_KH        0
#define ST_KL        8192
#define ST_VH        16384
#define ST_VL        24576
#define ATTN_SMEM_BYTES  98304
#define QPROJ_SMEM_BYTES 65536   // Ah,Al,Wh,Wl [128][64] bf16

// NOTE (pitfall, round 10): tcgen05/TMEM are compiled by this harness to the
// baseline 'sm_103' PTX target (no 'a' suffix) and are REJECTED by ptxas.
// mma.sync + ldmatrix are the tensor-core ceiling for this environment.

// Scratch (no dynamic allocation allowed).  All bf16 split pairs.
__device__ __nv_bfloat16 g_ah[BATCH * T1 * NFEAT];   // query hi/lo
__device__ __nv_bfloat16 g_al[BATCH * T1 * NFEAT];
__device__ __nv_bfloat16 g_wh[NFEAT * NFEAT];        // Wq hi/lo
__device__ __nv_bfloat16 g_wl[NFEAT * NFEAT];
__device__ __nv_bfloat16 g_qh[BATCH * T1 * NFEAT];   // projected Q hi/lo
__device__ __nv_bfloat16 g_ql[BATCH * T1 * NFEAT];
__device__ __nv_bfloat16 g_kh[BATCH * T2 * NFEAT];   // compacted K/V hi/lo
__device__ __nv_bfloat16 g_kl[BATCH * T2 * NFEAT];
__device__ __nv_bfloat16 g_vh[BATCH * T2 * NFEAT];
__device__ __nv_bfloat16 g_vl[BATCH * T2 * NFEAT];
__device__ int g_valid_idx[BATCH * T2];
__device__ int g_valid_cnt[BATCH];

__device__ __forceinline__ void prefetch_l2(const void* p) {
    asm volatile("prefetch.global.L2 [%0];" :: "l"(p));
}

// ---- bf16 split helpers -------------------------------------------------
__device__ __forceinline__ uint32_t pack_bf16(float x, float y) {
    __nv_bfloat162 t = __floats2bfloat162_rn(x, y);   // .x = x (low 16 bits)
    return *reinterpret_cast<uint32_t*>(&t);
}
__device__ __forceinline__ float bf16_res(float x) {
    return x - __bfloat162float(__float2bfloat16_rn(x));
}

// ---- smem swizzle: row-major [row][64] bf16, 8 x 16B chunks per 128B row.
__device__ __forceinline__ uint32_t swzb(int row, int ch) {
    return (uint32_t)(row * 128 + (((ch) ^ (row & 7)) << 4));
}

// ---- cp.async -----------------------------------------------------------
__device__ __forceinline__ void cp16(uint32_t dst, const void* src) {
    asm volatile("cp.async.cg.shared.global [%0], [%1], 16;" :: "r"(dst), "l"(src) : "memory");
}
__device__ __forceinline__ void cp_commit() {
    asm volatile("cp.async.commit_group;" ::: "memory");
}
__device__ __forceinline__ void cp_wait0() { asm volatile("cp.async.wait_group 0;" ::: "memory"); }
__device__ __forceinline__ void cp_wait1() { asm volatile("cp.async.wait_group 1;" ::: "memory"); }

// ---- tensor-core wrappers ----------------------------------------------
__device__ __forceinline__ void ldsm_x4(uint32_t* r, uint32_t addr) {
    asm volatile("ldmatrix.sync.aligned.m8n8.x4.shared.b16 {%0,%1,%2,%3}, [%4];"
        : "=r"(r[0]), "=r"(r[1]), "=r"(r[2]), "=r"(r[3]) : "r"(addr));
}
__device__ __forceinline__ void ldsm_x4_t(uint32_t* r, uint32_t addr) {
    asm volatile("ldmatrix.sync.aligned.m8n8.x4.trans.shared.b16 {%0,%1,%2,%3}, [%4];"
        : "=r"(r[0]), "=r"(r[1]), "=r"(r[2]), "=r"(r[3]) : "r"(addr));
}
__device__ __forceinline__ void mma16816(float* c, const uint32_t* a, uint32_t b0, uint32_t b1) {
    asm volatile("mma.sync.aligned.m16n8k16.row.col.f32.bf16.bf16.f32 "
        "{%0,%1,%2,%3}, {%4,%5,%6,%7}, {%8,%9}, {%0,%1,%2,%3};"
        : "+f"(c[0]), "+f"(c[1]), "+f"(c[2]), "+f"(c[3])
        : "r"(a[0]), "r"(a[1]), "r"(a[2]), "r"(a[3]), "r"(b0), "r"(b1));
}

// ---------------------------------------------------------------------------
// Kernel 1: per-batch compaction of valid (mask != 0) column indices.
// ---------------------------------------------------------------------------
__global__ void compact_mask_kernel(const int* __restrict__ mask) {
    const int b = blockIdx.x;
    const int lane = threadIdx.x;
    const int* m = mask + b * T2;
    int cnt = 0;
    for (int base = 0; base < T2; base += 32) {
        const int v = m[base + lane];
        const unsigned bal = __ballot_sync(0xffffffffu, v != 0);
        if (v)
            g_valid_idx[b * T2 + cnt + __popc(bal & ((1u << lane) - 1u))] = base + lane;
        cnt += __popc(bal);
    }
    if (lane == 0) g_valid_cnt[b] = cnt;
}

// ---------------------------------------------------------------------------
// Prepass A: elementwise fp32 -> (hi, lo) bf16 split.
// ---------------------------------------------------------------------------
__global__ void split_kernel(const float* __restrict__ src,
                             __nv_bfloat16* __restrict__ dh,
                             __nv_bfloat16* __restrict__ dl, int n4) {
    const int i = blockIdx.x * blockDim.x + threadIdx.x;
    if (i >= n4) return;
    const float4 f = ((const float4*)src)[i];
    uint2 hh, ll;
    hh.x = pack_bf16(f.x, f.y); hh.y = pack_bf16(f.z, f.w);
    ll.x = pack_bf16(bf16_res(f.x), bf16_res(f.y));
    ll.y = pack_bf16(bf16_res(f.z), bf16_res(f.w));
    ((uint2*)dh)[i] = hh;
    ((uint2*)dl)[i] = ll;
}

// ---------------------------------------------------------------------------
// Prepass B: gather-compact K/V rows by valid index, split to bf16 hi/lo.
// Rows >= cnt are zero-filled (masked tail: P=0 x V=0 in the attention PV).
// ---------------------------------------------------------------------------
__global__ void kv_split_kernel(const float* __restrict__ key,
                                const float* __restrict__ value) {
    const int j = blockIdx.x, b = blockIdx.y, t = threadIdx.x;
    const int cnt = g_valid_cnt[b];
    const size_t dst = ((size_t)b * T2 + j) * NFEAT + t * 4;
    if (j < cnt) {
        const int row = g_valid_idx[b * T2 + j];
        const size_t src = ((size_t)b * T2 + row) * NFEAT + t * 4;
        const float4 k = *(const float4*)(key + src);
        const float4 v = *(const float4*)(value + src);
        uint2 u;
        u.x = pack_bf16(k.x, k.y); u.y = pack_bf16(k.z, k.w);
        *(uint2*)&g_kh[dst] = u;
        u.x = pack_bf16(bf16_res(k.x), bf16_res(k.y));
        u.y = pack_bf16(bf16_res(k.z), bf16_res(k.w));
        *(uint2*)&g_kl[dst] = u;
        u.x = pack_bf16(v.x, v.y); u.y = pack_bf16(v.z, v.w);
        *(uint2*)&g_vh[dst] = u;
        u.x = pack_bf16(bf16_res(v.x), bf16_res(v.y));
        u.y = pack_bf16(bf16_res(v.z), bf16_res(v.w));
        *(uint2*)&g_vl[dst] = u;
    } else {
        const uint2 z = make_uint2(0u, 0u);
        *(uint2*)&g_kh[dst] = z;
        *(uint2*)&g_kl[dst] = z;
        *(uint2*)&g_vh[dst] = z;
        *(uint2*)&g_vl[dst] = z;
    }
}

// ---------------------------------------------------------------------------
// Kernel 2: Q projection GEMM (mma.sync split-bf16, 3-pass), cp.async staging.
// ---------------------------------------------------------------------------
__global__ __launch_bounds__(256, 2)
void qproj_kernel(const float* __restrict__ bias) {
    extern __shared__ __align__(16) unsigned char qsm[];
    unsigned char* Ah = qsm;               // 128*128B = 16384
    unsigned char* Al = qsm + 16384;
    unsigned char* Wh = qsm + 32768;
    unsigned char* Wl = qsm + 49152;       // end 65536

    const uint32_t sAh = (uint32_t)__cvta_generic_to_shared(Ah);
    const uint32_t sAl = (uint32_t)__cvta_generic_to_shared(Al);
    const uint32_t sWh = (uint32_t)__cvta_generic_to_shared(Wh);
    const uint32_t sWl = (uint32_t)__cvta_generic_to_shared(Wl);

    const int tid  = threadIdx.x;
    const int lane = tid & 31;
    const int w    = tid >> 5;
    const int bm   = blockIdx.y * 128;
    const int bn   = blockIdx.x * 128;

    float s[16][4];
#pragma unroll
    for (int tt = 0; tt < 16; tt++)
#pragma unroll
        for (int r = 0; r < 4; r++) s[tt][r] = 0.f;

    const int lrow = tid >> 3;       // 0..31 (+p*32)
    const int lc   = tid & 7;        // 16B chunk

    for (int kc = 0; kc < NFEAT / 64; kc++) {
        const int k0 = kc * 64;
        __syncthreads();   // previous chunk consumed
#pragma unroll
        for (int p = 0; p < 4; p++) {
            const int row = lrow + p * 32;
            const size_t aoff = (size_t)(bm + row) * NFEAT + k0 + lc * 8;
            const size_t woff = (size_t)(bn + row) * NFEAT + k0 + lc * 8;
            if (kc + 1 < NFEAT / 64) {
                prefetch_l2(&g_ah[aoff + 64]);
                prefetch_l2(&g_wh[woff + 64]);
            }
            const uint32_t sw = swzb(row, lc);
            cp16(sAh + sw, &g_ah[aoff]);
            cp16(sAl + sw, &g_al[aoff]);
            cp16(sWh + sw, &g_wh[woff]);
            cp16(sWl + sw, &g_wl[woff]);
        }
        cp_commit();
        cp_wait0();
        __syncthreads();

#pragma unroll
        for (int ks = 0; ks < 4; ks++) {
            uint32_t qh[4], ql[4];
            {
                const int row = w * 16 + (lane & 15);
                const int ch  = 2 * ks + (lane >> 4);
                ldsm_x4(qh, sAh + swzb(row, ch));
                ldsm_x4(ql, sAl + swzb(row, ch));
            }
#pragma unroll
            for (int tp = 0; tp < 8; tp++) {
                uint32_t kh[4], kl[4];
                const int jrow = tp * 16 + ((lane >> 4) << 3) + (lane & 7);
                const int kch  = 2 * ks + ((lane >> 3) & 1);
                ldsm_x4(kh, sWh + swzb(jrow, kch));
                ldsm_x4(kl, sWl + swzb(jrow, kch));
                mma16816(s[2 * tp],     qh, kh[0], kh[1]);
                mma16816(s[2 * tp],     qh, kl[0], kl[1]);
                mma16816(s[2 * tp],     ql, kh[0], kh[1]);
                mma16816(s[2 * tp + 1], qh, kh[2], kh[3]);
                mma16816(s[2 * tp + 1], qh, kl[2], kl[3]);
                mma16816(s[2 * tp + 1], ql, kh[2], kh[3]);
            }
        }
    }

    // ---- epilogue: bias add in fp32, split to bf16 hi/lo, store ----
    const int row0 = bm + w * 16 + (lane >> 2);
#pragma unroll
    for (int tt = 0; tt < 16; tt++) {
        const int col = bn + tt * 8 + (lane & 3) * 2;
        const float2 bv = *(const float2*)(bias + col);
        const float x0 = s[tt][0] + bv.x, x1 = s[tt][1] + bv.y;
        const float x2 = s[tt][2] + bv.x, x3 = s[tt][3] + bv.y;
        const size_t o0 = (size_t)row0 * NFEAT + col;
        const size_t o1 = (size_t)(row0 + 8) * NFEAT + col;
        *(uint32_t*)&g_qh[o0] = pack_bf16(x0, x1);
        *(uint32_t*)&g_ql[o0] = pack_bf16(bf16_res(x0), bf16_res(x1));
        *(uint32_t*)&g_qh[o1] = pack_bf16(x2, x3);
        *(uint32_t*)&g_ql[o1] = pack_bf16(bf16_res(x2), bf16_res(x3));
    }
}

// ---------------------------------------------------------------------------
// Kernel 3: split-bf16 mma.sync flash attention (banked r9 version, unchanged).
// ---------------------------------------------------------------------------
__global__ __launch_bounds__(256, 2)
void attn_kernel(float* __restrict__ out) {
    extern __shared__ __align__(16) unsigned char smem[];
    const uint32_t sbase = (uint32_t)__cvta_generic_to_shared(smem);

    const int tid  = threadIdx.x;
    const int lane = tid & 31;
    const int w    = tid >> 5;
    const int blk  = blockIdx.x;
    const int qt = blk & 15;
    const int h  = (blk >> 4) & 15;
    const int b  = blk >> 8;
    const int q0 = qt * BQ;

    const int cnt = g_valid_cnt[b];
    float* outbase = out + (size_t)(b * T1 + q0) * NFEAT + h * DK;

    if (cnt == 0) {
        const float4 z = make_float4(0.f, 0.f, 0.f, 0.f);
#pragma unroll
        for (int p = 0; p < 8; p++) {
            const int idx = tid + p * 256;
            *(float4*)(outbase + (size_t)(idx >> 4) * NFEAT + (idx & 15) * 4) = z;
        }
        return;
    }

    const size_t kvbase = (size_t)b * T2 * NFEAT + h * DK;
    const int ntiles = (cnt + BK - 1) / BK;

#pragma unroll
    for (int p = 0; p < 4; p++) {
        const int idx = tid + p * 256;
        const int row = idx >> 3, c = idx & 7;
        const size_t off = (size_t)(b * T1 + q0 + row) * NFEAT + h * DK + c * 8;
        cp16(sbase + SM_QH + swzb(row, c), &g_qh[off]);
        cp16(sbase + SM_QL + swzb(row, c), &g_ql[off]);
    }
#pragma unroll
    for (int p = 0; p < 2; p++) {
        const int idx = tid + p * 256;
        const int row = idx >> 3, c = idx & 7;
        const size_t off = kvbase + (size_t)row * NFEAT + c * 8;
        const uint32_t sw = swzb(row, c);
        const uint32_t st = sbase + SM_STAGE(0);
        cp16(st + ST_KH + sw, &g_kh[off]);
        cp16(st + ST_KL + sw, &g_kl[off]);
        cp16(st + ST_VH + sw, &g_vh[off]);
        cp16(st + ST_VL + sw, &g_vl[off]);
    }
    cp_commit();

    float s[8][4], o[8][4];
    float m0 = -INFINITY, m1 = -INFINITY, l0 = 0.f, l1 = 0.f;
#pragma unroll
    for (int tt = 0; tt < 8; tt++)
#pragma unroll
        for (int r = 0; r < 4; r++) o[tt][r] = 0.f;

    for (int t = 0; t < ntiles; t++) {
        const int kv0 = t * BK;
        if (t + 1 < ntiles) {
#pragma unroll
            for (int p = 0; p < 2; p++) {
                const int idx = tid + p * 256;
                const int row = idx >> 3, c = idx & 7;
                const size_t off = kvbase + (size_t)(kv0 + BK + row) * NFEAT + c * 8;
                const uint32_t sw = swzb(row, c);
                const uint32_t st = sbase + SM_STAGE((t + 1) & 1);
                cp16(st + ST_KH + sw, &g_kh[off]);
                cp16(st + ST_KL + sw, &g_kl[off]);
                cp16(st + ST_VH + sw, &g_vh[off]);
                cp16(st + ST_VL + sw, &g_vl[off]);
            }
            cp_commit();
            cp_wait1();
        } else {
            cp_wait0();
        }
        __syncthreads();

        const uint32_t st = sbase + SM_STAGE(t & 1);
        const uint32_t sKh = st + ST_KH, sKl = st + ST_KL;
        const uint32_t sVh = st + ST_VH, sVl = st + ST_VL;

#pragma unroll
        for (int tt = 0; tt < 8; tt++)
#pragma unroll
            for (int r = 0; r < 4; r++) s[tt][r] = 0.f;

        const int r0 = w * 16;
#pragma unroll
        for (int ks = 0; ks < 4; ks++) {
            uint32_t qh[4], ql[4];
            {
                const int row = r0 + (lane & 15);
                const int ch  = 2 * ks + (lane >> 4);
                ldsm_x4(qh, sbase + SM_QH + swzb(row, ch));
                ldsm_x4(ql, sbase + SM_QL + swzb(row, ch));
            }
#pragma unroll
            for (int tp = 0; tp < 4; tp++) {
                uint32_t kh[4], kl[4];
                const int jrow = tp * 16 + ((lane >> 4) << 3) + (lane & 7);
                const int kch  = 2 * ks + ((lane >> 3) & 1);
                ldsm_x4(kh, sKh + swzb(jrow, kch));
                ldsm_x4(kl, sKl + swzb(jrow, kch));
                mma16816(s[2 * tp],     qh, kh[0], kh[1]);
                mma16816(s[2 * tp],     qh, kl[0], kl[1]);
                mma16816(s[2 * tp],     ql, kh[0], kh[1]);
                mma16816(s[2 * tp + 1], qh, kh[2], kh[3]);
                mma16816(s[2 * tp + 1], qh, kl[2], kl[3]);
                mma16816(s[2 * tp + 1], ql, kh[2], kh[3]);
            }
        }

        const int cb = (lane & 3) * 2;
#pragma unroll
        for (int tt = 0; tt < 8; tt++) {
            const int j0 = kv0 + tt * 8 + cb;
            s[tt][0] = (j0     < cnt) ? s[tt][0] * 0.125f : -INFINITY;
            s[tt][1] = (j0 + 1 < cnt) ? s[tt][1] * 0.125f : -INFINITY;
            s[tt][2] = (j0     < cnt) ? s[tt][2] * 0.125f : -INFINITY;
            s[tt][3] = (j0 + 1 < cnt) ? s[tt][3] * 0.125f : -INFINITY;
        }
        float v0 = -INFINITY, v1 = -INFINITY;
#pragma unroll
        for (int tt = 0; tt < 8; tt++) {
            v0 = fmaxf(v0, fmaxf(s[tt][0], s[tt][1]));
            v1 = fmaxf(v1, fmaxf(s[tt][2], s[tt][3]));
        }
        v0 = fmaxf(v0, __shfl_xor_sync(0xffffffffu, v0, 1));
        v0 = fmaxf(v0, __shfl_xor_sync(0xffffffffu, v0, 2));
        v1 = fmaxf(v1, __shfl_xor_sync(0xffffffffu, v1, 1));
        v1 = fmaxf(v1, __shfl_xor_sync(0xffffffffu, v1, 2));
        const float mn0 = fmaxf(m0, v0), mn1 = fmaxf(m1, v1);
        const float corr0 = __expf(m0 - mn0), corr1 = __expf(m1 - mn1);
        m0 = mn0; m1 = mn1;
        float rs0 = 0.f, rs1 = 0.f;
#pragma unroll
        for (int tt = 0; tt < 8; tt++) {
            s[tt][0] = __expf(s[tt][0] - mn0);
            s[tt][1] = __expf(s[tt][1] - mn0);
            s[tt][2] = __expf(s[tt][2] - mn1);
            s[tt][3] = __expf(s[tt][3] - mn1);
            rs0 += s[tt][0] + s[tt][1];
            rs1 += s[tt][2] + s[tt][3];
        }
        rs0 += __shfl_xor_sync(0xffffffffu, rs0, 1);
        rs0 += __shfl_xor_sync(0xffffffffu, rs0, 2);
        rs1 += __shfl_xor_sync(0xffffffffu, rs1, 1);
        rs1 += __shfl_xor_sync(0xffffffffu, rs1, 2);
        l0 = l0 * corr0 + rs0;
        l1 = l1 * corr1 + rs1;
#pragma unroll
        for (int tt = 0; tt < 8; tt++) {
            o[tt][0] *= corr0; o[tt][1] *= corr0;
            o[tt][2] *= corr1; o[tt][3] *= corr1;
        }

#pragma unroll
        for (int ks = 0; ks < 4; ks++) {
            uint32_t aH[4], aL[4];
            aH[0] = pack_bf16(s[2 * ks][0], s[2 * ks][1]);
            aH[1] = pack_bf16(s[2 * ks][2], s[2 * ks][3]);
            aH[2] = pack_bf16(s[2 * ks + 1][0], s[2 * ks + 1][1]);
            aH[3] = pack_bf16(s[2 * ks + 1][2], s[2 * ks + 1][3]);
            aL[0] = pack_bf16(bf16_res(s[2 * ks][0]), bf16_res(s[2 * ks][1]));
            aL[1] = pack_bf16(bf16_res(s[2 * ks][2]), bf16_res(s[2 * ks][3]));
            aL[2] = pack_bf16(bf16_res(s[2 * ks + 1][0]), bf16_res(s[2 * ks + 1][1]));
            aL[3] = pack_bf16(bf16_res(s[2 * ks + 1][2]), bf16_res(s[2 * ks + 1][3]));
#pragma unroll
            for (int tp = 0; tp < 4; tp++) {
                uint32_t vh[4], vl[4];
                const int vrow = ks * 16 + (((lane >> 3) & 1) << 3) + (lane & 7);
                const int vch  = 2 * tp + (lane >> 4);
                ldsm_x4_t(vh, sVh + swzb(vrow, vch));
                ldsm_x4_t(vl, sVl + swzb(vrow, vch));
                mma16816(o[2 * tp],     aH, vh[0], vh[1]);
                mma16816(o[2 * tp],     aH, vl[0], vl[1]);
                mma16816(o[2 * tp],     aL, vh[0], vh[1]);
                mma16816(o[2 * tp + 1], aH, vh[2], vh[3]);
                mma16816(o[2 * tp + 1], aH, vl[2], vl[3]);
                mma16816(o[2 * tp + 1], aL, vh[2], vh[3]);
            }
        }
        __syncthreads();
    }

    const int row0 = w * 16 + (lane >> 2);
    const float inv0 = 1.0f / l0, inv1 = 1.0f / l1;
#pragma unroll
    for (int tt = 0; tt < 8; tt++) {
        const int col = tt * 8 + (lane & 3) * 2;
        *(float2*)(outbase + (size_t)row0 * NFEAT + col) =
            make_float2(o[tt][0] * inv0, o[tt][1] * inv0);
        *(float2*)(outbase + (size_t)(row0 + 8) * NFEAT + col) =
            make_float2(o[tt][2] * inv1, o[tt][3] * inv1);
    }
}

// ---------------------------------------------------------------------------
// Entry point.  Inputs per metadata order: query, key, value, mask, Wq, bq.
// ---------------------------------------------------------------------------
extern "C" void kernel_launch(void* const* d_in, const int* in_sizes, int n_in,
                              void* d_out, int out_size) {
    const float* query = (const float*)d_in[0];
    const float* key   = (const float*)d_in[1];
    const float* value = (const float*)d_in[2];
    const int*   mask  = (const int*)  d_in[3];
    const float* Wq    = (const float*)d_in[4];
    const float* bq    = (const float*)d_in[5];
    float* out = (float*)d_out;

    __nv_bfloat16 *p_ah, *p_al, *p_wh, *p_wl;
    cudaGetSymbolAddress((void**)&p_ah, g_ah);
    cudaGetSymbolAddress((void**)&p_al, g_al);
    cudaGetSymbolAddress((void**)&p_wh, g_wh);
    cudaGetSymbolAddress((void**)&p_wl, g_wl);

    cudaFuncSetAttribute(attn_kernel,
                         cudaFuncAttributeMaxDynamicSharedMemorySize,
                         ATTN_SMEM_BYTES);
    cudaFuncSetAttribute(qproj_kernel,
                         cudaFuncAttributeMaxDynamicSharedMemorySize,
                         QPROJ_SMEM_BYTES);

    compact_mask_kernel<<<BATCH, 32>>>(mask);
    {
        const int nA4 = BATCH * T1 * NFEAT / 4;
        split_kernel<<<(nA4 + 255) / 256, 256>>>(query, p_ah, p_al, nA4);
        const int nW4 = NFEAT * NFEAT / 4;
        split_kernel<<<(nW4 + 255) / 256, 256>>>(Wq, p_wh, p_wl, nW4);
    }
    kv_split_kernel<<<dim3(T2, BATCH), 256>>>(key, value);
    qproj_kernel<<<dim3(NFEAT / 128, (BATCH * T1) / 128), 256, QPROJ_SMEM_BYTES>>>(bq);
    attn_kernel<<<BATCH * NH * (T1 / BQ), 256, ATTN_SMEM_BYTES>>>(out);
}